// round 3
// baseline (speedup 1.0000x reference)
#include <cuda_runtime.h>
#include <cuda_bf16.h>

#define N_NODES 50000
#define N_EDGES 800000
#define D_IN    96
#define D_EDGE  32
#define D_OUT   96
#define N_TYPES 4

typedef unsigned long long ull;

#define PACKF2(dst, lo, hi) \
    asm("mov.b64 %0, {%1, %2};" : "=l"(dst) : "f"(lo), "f"(hi))
#define UNPACKF2(lo, hi, src) \
    asm("mov.b64 {%0, %1}, %2;" : "=f"(lo), "=f"(hi) : "l"(src))
// packed dual-FMA: acc.lo += a.lo*b.lo ; acc.hi += a.hi*b.hi
#define FFMA2(acc, a, b) \
    asm("fma.rn.f32x2 %0, %1, %2, %0;" : "+l"(acc) : "l"(a), "l"(b))

// Scratch: y[t][n][j] = 0.25 * (x[n] @ W_x[t] + b[t])   (76.8 MB, L2-resident)
__device__ float g_y[(size_t)N_TYPES * N_NODES * D_OUT];

// ---------------------------------------------------------------------------
// Kernel A: y[t][n] = 0.25*(x[n] @ W_x[t] + b[t]),  k-pair packed FFMA2.
// Grid: (ceil(N/64), 4). Block: 256 threads; each warp owns 8 nodes.
// Even/odd-k partial sums live in one f32x2 accumulator; horizontal add at end.
// ---------------------------------------------------------------------------
#define WXPAD (D_IN + 2)   // 98: rows 8B-aligned, lane*49+kp coprime-32 banks

__global__ __launch_bounds__(256) void precompute_y_kernel(
    const float* __restrict__ x,      // [N, 96]
    const float* __restrict__ W,      // [4, 128, 96]
    const float* __restrict__ b)      // [4, 96]
{
    const int t     = blockIdx.y;
    const int node0 = blockIdx.x * 64;

    __shared__ __align__(8) float Wt_sm[D_OUT][WXPAD];  // 37.6 KB, transposed
    __shared__ __align__(8) float xs[64][D_IN];         // 24 KB, row-major
    __shared__ float bsm[D_OUT];

    // transposed W fill: coalesced global read, 2-way STS conflict (one-time)
    const float* Wt = W + (size_t)t * 128 * 96;
    for (int i = threadIdx.x; i < D_IN * D_OUT; i += blockDim.x) {
        int k = i / D_OUT, c = i - k * D_OUT;
        Wt_sm[c][k] = 0.25f * Wt[i];
    }
    if (threadIdx.x < D_OUT)
        bsm[threadIdx.x] = 0.25f * b[t * D_OUT + threadIdx.x];
    // coalesced x fill, row-major (consecutive lanes -> consecutive c)
    for (int i = threadIdx.x; i < 64 * D_IN; i += blockDim.x) {
        int r = i / D_IN, c = i - r * D_IN;
        int n = node0 + r;
        xs[r][c] = (n < N_NODES) ? x[(size_t)n * D_IN + c] : 0.0f;
    }
    __syncthreads();

    const int wid  = threadIdx.x >> 5;
    const int lane = threadIdx.x & 31;
    const int i0   = wid * 8;

    ull acc[8][3];
#pragma unroll
    for (int i = 0; i < 8; i++)
        acc[i][0] = acc[i][1] = acc[i][2] = 0ull;

#pragma unroll 4
    for (int kp = 0; kp < D_IN / 2; kp++) {
        ull W0 = *reinterpret_cast<const ull*>(&Wt_sm[lane     ][2 * kp]);
        ull W1 = *reinterpret_cast<const ull*>(&Wt_sm[lane + 32][2 * kp]);
        ull W2 = *reinterpret_cast<const ull*>(&Wt_sm[lane + 64][2 * kp]);
#pragma unroll
        for (int i = 0; i < 8; i++) {
            ull xv2 = *reinterpret_cast<const ull*>(&xs[i0 + i][2 * kp]);  // bcast
            FFMA2(acc[i][0], xv2, W0);
            FFMA2(acc[i][1], xv2, W1);
            FFMA2(acc[i][2], xv2, W2);
        }
    }

    float b0 = bsm[lane], b1 = bsm[lane + 32], b2 = bsm[lane + 64];
#pragma unroll
    for (int i = 0; i < 8; i++) {
        int n = node0 + i0 + i;
        if (n < N_NODES) {
            float lo, hi;
            float* yp = g_y + ((size_t)t * N_NODES + n) * D_OUT;
            UNPACKF2(lo, hi, acc[i][0]); yp[lane]      = b0 + lo + hi;
            UNPACKF2(lo, hi, acc[i][1]); yp[lane + 32] = b1 + lo + hi;
            UNPACKF2(lo, hi, acc[i][2]); yp[lane + 64] = b2 + lo + hi;
        }
    }
}

// ---------------------------------------------------------------------------
// Kernel B: edge kernel, k-pair packed FFMA2.
// One relation type per block (blockIdx.y); warps compact matching edges
// (ballot+rank) into a queue, process batches of 8.
// out[dst] += y[t][src] + 0.25 * (|ef[s]-ef[d]| @ W_e[t])
// y folds into the accumulator init: acc = pack(y, 0).
// ---------------------------------------------------------------------------
#define EK_WARPS 8
#define BATCH    8
#define QCAP     40
#define WEPAD (D_EDGE + 2)   // 34: rows 8B-aligned, lane*17+kp coprime-32 banks

__global__ __launch_bounds__(256) void edge_kernel(
    const float* __restrict__ ef,     // [N, 32]
    const int*   __restrict__ src,    // [E]
    const int*   __restrict__ dst,    // [E]
    const int*   __restrict__ et,     // [E]
    const float* __restrict__ W,      // [4, 128, 96]
    float*       __restrict__ out)    // [N, 96]
{
    const int t = blockIdx.y;

    __shared__ __align__(8) float Wt_sm[D_OUT][WEPAD];          // 13 KB, transposed
    __shared__ int   eidx[EK_WARPS][QCAP];
    __shared__ __align__(8) float esm[EK_WARPS][BATCH][WEPAD];  // 8.7 KB, edge-major

    // rows 96..127 of W[t] = W_e, scaled 1/4, stored transposed [c][k]
    const float* Wt = W + (size_t)t * 128 * 96 + 96 * 96;
    for (int i = threadIdx.x; i < D_EDGE * D_OUT; i += blockDim.x) {
        int k = i / D_OUT, c = i - k * D_OUT;
        Wt_sm[c][k] = 0.25f * Wt[i];
    }
    __syncthreads();

    const int wid  = threadIdx.x >> 5;
    const int lane = threadIdx.x & 31;
    const unsigned lanemask_lt = (1u << lane) - 1u;

    const long gw     = (long)blockIdx.x * EK_WARPS + wid;
    const long stride = (long)gridDim.x * EK_WARPS * 32;

    long base = gw * 32;
    int  q    = 0;

    while (true) {
        while (q < BATCH && base < N_EDGES) {
            long eid = base + lane;
            bool ok  = (eid < N_EDGES) && (et[eid] == t);
            unsigned m = __ballot_sync(0xffffffffu, ok);
            int rank = __popc(m & lanemask_lt);
            if (ok) eidx[wid][q + rank] = (int)eid;
            q    += __popc(m);
            base += stride;
        }
        __syncwarp();
        if (q == 0) break;

        const int B = (q < BATCH) ? q : BATCH;   // warp-uniform

        int s[BATCH], d[BATCH];
        // |ef[s]-ef[d]| edge-major: lane writes its k=lane element (conflict-free)
#pragma unroll
        for (int i = 0; i < BATCH; i++) {
            int e2 = (i < B) ? eidx[wid][i] : eidx[wid][0];
            s[i] = src[e2];
            d[i] = dst[e2];
            float a  = ef[(size_t)s[i] * D_EDGE + lane];
            float bb = ef[(size_t)d[i] * D_EDGE + lane];
            esm[wid][i][lane] = fabsf(a - bb);
        }
        __syncwarp();

        // acc init = pack(y[t][src], 0): even/odd-k partials accumulate on top
        ull acc[BATCH][3];
#pragma unroll
        for (int i = 0; i < BATCH; i++) {
            const float* yp = g_y + ((size_t)t * N_NODES + s[i]) * D_OUT;
            PACKF2(acc[i][0], yp[lane],      0.0f);
            PACKF2(acc[i][1], yp[lane + 32], 0.0f);
            PACKF2(acc[i][2], yp[lane + 64], 0.0f);
        }

#pragma unroll 4
        for (int kp = 0; kp < D_EDGE / 2; kp++) {
            ull W0 = *reinterpret_cast<const ull*>(&Wt_sm[lane     ][2 * kp]);
            ull W1 = *reinterpret_cast<const ull*>(&Wt_sm[lane + 32][2 * kp]);
            ull W2 = *reinterpret_cast<const ull*>(&Wt_sm[lane + 64][2 * kp]);
#pragma unroll
            for (int i = 0; i < BATCH; i++) {
                ull ev2 = *reinterpret_cast<const ull*>(&esm[wid][i][2 * kp]); // bcast
                FFMA2(acc[i][0], ev2, W0);
                FFMA2(acc[i][1], ev2, W1);
                FFMA2(acc[i][2], ev2, W2);
            }
        }

#pragma unroll
        for (int i = 0; i < BATCH; i++) {
            if (i < B) {
                float* op = out + (size_t)d[i] * D_OUT;
                float lo, hi;
                UNPACKF2(lo, hi, acc[i][0]); atomicAdd(op + lane,      lo + hi);
                UNPACKF2(lo, hi, acc[i][1]); atomicAdd(op + lane + 32, lo + hi);
                UNPACKF2(lo, hi, acc[i][2]); atomicAdd(op + lane + 64, lo + hi);
            }
        }

        int rem = q - B;
        int tmp = 0;
        __syncwarp();
        if (lane < rem) tmp = eidx[wid][B + lane];
        __syncwarp();
        if (lane < rem) eidx[wid][lane] = tmp;
        __syncwarp();
        q = rem;
    }
}

// ---------------------------------------------------------------------------
extern "C" void kernel_launch(void* const* d_in, const int* in_sizes, int n_in,
                              void* d_out, int out_size)
{
    const float* x   = (const float*)d_in[0];          // [N, 96]
    const float* ef  = (const float*)d_in[1];          // [N, 32]
    const int*   ei  = (const int*)  d_in[2];          // [2, E]
    const int*   et  = (const int*)  d_in[3];          // [E]
    const float* W   = (const float*)d_in[4];          // [4, 128, 96]
    const float* b   = (const float*)d_in[5];          // [4, 96]
    float*       out = (float*)d_out;                  // [N, 96]

    const int* srcp = ei;
    const int* dstp = ei + N_EDGES;

    cudaMemsetAsync(out, 0, (size_t)out_size * sizeof(float), 0);

    {
        dim3 grid((N_NODES + 63) / 64, N_TYPES);
        precompute_y_kernel<<<grid, 256>>>(x, W, b);
    }
    {
        dim3 grid(296, N_TYPES);
        edge_kernel<<<grid, 256>>>(ef, srcp, dstp, et, W, out);
    }
}

// round 4
// speedup vs baseline: 1.2344x; 1.2344x over previous
#include <cuda_runtime.h>
#include <cuda_bf16.h>

#define N_NODES 50000
#define N_EDGES 800000
#define D_IN    96
#define D_EDGE  32
#define D_OUT   96
#define N_TYPES 4

typedef unsigned long long ull;

#define PACKF2(dst, lo, hi) \
    asm("mov.b64 %0, {%1, %2};" : "=l"(dst) : "f"(lo), "f"(hi))
#define UNPACKF2(lo, hi, src) \
    asm("mov.b64 {%0, %1}, %2;" : "=f"(lo), "=f"(hi) : "l"(src))
// packed dual-FMA: acc.lo += a.lo*b.lo ; acc.hi += a.hi*b.hi
#define FFMA2(acc, a, b) \
    asm("fma.rn.f32x2 %0, %1, %2, %0;" : "+l"(acc) : "l"(a), "l"(b))

// Scratch: y[t][n][j] = 0.25 * (x[n] @ W_x[t] + b[t])   (76.8 MB, L2-resident)
__device__ float g_y[(size_t)N_TYPES * N_NODES * D_OUT];

// ---------------------------------------------------------------------------
// Kernel A: y[t][n] = 0.25*(x[n] @ W_x[t] + b[t]),  NODE-PAIR packed FFMA2.
// acc = (node 2p, node 2p+1) per output column -> register count == scalar.
// x tile stored transposed xs_t[k][node] (stride 66: 8B-aligned rows, fill is
// coalesced in gmem and only 2-way conflicted in the one-time STS).
// ---------------------------------------------------------------------------
#define XT_STRIDE 66

__global__ __launch_bounds__(256) void precompute_y_kernel(
    const float* __restrict__ x,      // [N, 96]
    const float* __restrict__ W,      // [4, 128, 96]
    const float* __restrict__ b)      // [4, 96]
{
    const int t     = blockIdx.y;
    const int node0 = blockIdx.x * 64;

    __shared__ float Wsm[D_IN][D_OUT];                     // 36 KB (0.25*W_x[t])
    __shared__ __align__(8) float xs_t[D_IN][XT_STRIDE];   // 25.3 KB transposed
    __shared__ float bsm[D_OUT];

    const float* Wt = W + (size_t)t * 128 * 96;
    for (int i = threadIdx.x; i < D_IN * D_OUT; i += blockDim.x)
        (&Wsm[0][0])[i] = 0.25f * Wt[i];
    if (threadIdx.x < D_OUT)
        bsm[threadIdx.x] = 0.25f * b[t * D_OUT + threadIdx.x];
    // coalesced gmem read (consecutive threads -> consecutive c of one row),
    // transpose at the STS (2-way bank conflict, one-time)
    for (int i = threadIdx.x; i < 64 * D_IN; i += blockDim.x) {
        int r = i / D_IN, c = i - r * D_IN;
        int n = node0 + r;
        xs_t[c][r] = (n < N_NODES) ? x[(size_t)n * D_IN + c] : 0.0f;
    }
    __syncthreads();

    const int wid  = threadIdx.x >> 5;
    const int lane = threadIdx.x & 31;
    const int i0   = wid * 8;                 // 8 nodes per warp = 4 pairs

    ull acc[4][3];
    {
        float b0 = bsm[lane], b1 = bsm[lane + 32], b2 = bsm[lane + 64];
        ull B0, B1, B2;
        PACKF2(B0, b0, b0); PACKF2(B1, b1, b1); PACKF2(B2, b2, b2);
#pragma unroll
        for (int p = 0; p < 4; p++) { acc[p][0] = B0; acc[p][1] = B1; acc[p][2] = B2; }
    }

#pragma unroll 8
    for (int k = 0; k < D_IN; k++) {
        float w0 = Wsm[k][lane];
        float w1 = Wsm[k][lane + 32];
        float w2 = Wsm[k][lane + 64];
        ull W0, W1, W2;
        PACKF2(W0, w0, w0); PACKF2(W1, w1, w1); PACKF2(W2, w2, w2);
#pragma unroll
        for (int p = 0; p < 4; p++) {
            ull xv2 = *reinterpret_cast<const ull*>(&xs_t[k][i0 + 2 * p]); // bcast
            FFMA2(acc[p][0], xv2, W0);
            FFMA2(acc[p][1], xv2, W1);
            FFMA2(acc[p][2], xv2, W2);
        }
    }

#pragma unroll
    for (int p = 0; p < 4; p++) {
        int n_lo = node0 + i0 + 2 * p;
        int n_hi = n_lo + 1;
        float* y_lo = g_y + ((size_t)t * N_NODES + n_lo) * D_OUT;
        float* y_hi = g_y + ((size_t)t * N_NODES + n_hi) * D_OUT;
#pragma unroll
        for (int c = 0; c < 3; c++) {
            float lo, hi;
            UNPACKF2(lo, hi, acc[p][c]);
            if (n_lo < N_NODES) y_lo[lane + 32 * c] = lo;
            if (n_hi < N_NODES) y_hi[lane + 32 * c] = hi;
        }
    }
}

// ---------------------------------------------------------------------------
// Kernel B: edge kernel, EDGE-PAIR packed FFMA2 (R2 verbatim: measured 222us,
// regs 64, occ 42.8%). One relation type per block row; ballot-compacted
// per-warp edge queue, batches of 8 edges = 4 packed pairs.
// out[dst] += y[t][src] + 0.25 * (|ef[s]-ef[d]| @ W_e[t])
// ---------------------------------------------------------------------------
#define EK_WARPS   8
#define BATCH      8
#define QCAP       40
#define ESM_STRIDE 10

__global__ __launch_bounds__(256) void edge_kernel(
    const float* __restrict__ ef,     // [N, 32]
    const int*   __restrict__ src,    // [E]
    const int*   __restrict__ dst,    // [E]
    const int*   __restrict__ et,     // [E]
    const float* __restrict__ W,      // [4, 128, 96]
    float*       __restrict__ out)    // [N, 96]
{
    const int t = blockIdx.y;

    __shared__ __align__(8) float2 Wdup[D_EDGE][D_OUT];              // 24 KB
    __shared__ int   eidx[EK_WARPS][QCAP];
    __shared__ __align__(8) float esm[EK_WARPS][D_EDGE][ESM_STRIDE]; // 10 KB

    const float* Wt = W + (size_t)t * 128 * 96 + 96 * 96;
    for (int i = threadIdx.x; i < D_EDGE * D_OUT; i += blockDim.x) {
        float w = 0.25f * Wt[i];
        (&Wdup[0][0])[i] = make_float2(w, w);
    }
    __syncthreads();

    const int wid  = threadIdx.x >> 5;
    const int lane = threadIdx.x & 31;
    const unsigned lanemask_lt = (1u << lane) - 1u;

    const long gw     = (long)blockIdx.x * EK_WARPS + wid;
    const long stride = (long)gridDim.x * EK_WARPS * 32;

    long base = gw * 32;
    int  q    = 0;

    while (true) {
        while (q < BATCH && base < N_EDGES) {
            long eid = base + lane;
            bool ok  = (eid < N_EDGES) && (et[eid] == t);
            unsigned m = __ballot_sync(0xffffffffu, ok);
            int rank = __popc(m & lanemask_lt);
            if (ok) eidx[wid][q + rank] = (int)eid;
            q    += __popc(m);
            base += stride;
        }
        __syncwarp();
        if (q == 0) break;

        const int B = (q < BATCH) ? q : BATCH;   // warp-uniform

        int s[BATCH], d[BATCH];
#pragma unroll
        for (int i = 0; i < BATCH; i++) {
            int e2 = (i < B) ? eidx[wid][i] : eidx[wid][0];
            s[i] = src[e2];
            d[i] = dst[e2];
            float a  = ef[(size_t)s[i] * D_EDGE + lane];
            float bb = ef[(size_t)d[i] * D_EDGE + lane];
            esm[wid][lane][i] = fabsf(a - bb);
        }
        __syncwarp();

        ull acc[4][3];
#pragma unroll
        for (int p = 0; p < 4; p++) {
            const float* y0 = g_y + ((size_t)t * N_NODES + s[2 * p])     * D_OUT;
            const float* y1 = g_y + ((size_t)t * N_NODES + s[2 * p + 1]) * D_OUT;
#pragma unroll
            for (int c = 0; c < 3; c++) {
                float lo = y0[lane + 32 * c];
                float hi = y1[lane + 32 * c];
                PACKF2(acc[p][c], lo, hi);
            }
        }

#pragma unroll 8
        for (int k = 0; k < D_EDGE; k++) {
            ull W0 = *reinterpret_cast<const ull*>(&Wdup[k][lane]);
            ull W1 = *reinterpret_cast<const ull*>(&Wdup[k][lane + 32]);
            ull W2 = *reinterpret_cast<const ull*>(&Wdup[k][lane + 64]);
#pragma unroll
            for (int p = 0; p < 4; p++) {
                ull ev2 = *reinterpret_cast<const ull*>(&esm[wid][k][2 * p]);
                FFMA2(acc[p][0], ev2, W0);
                FFMA2(acc[p][1], ev2, W1);
                FFMA2(acc[p][2], ev2, W2);
            }
        }

#pragma unroll
        for (int p = 0; p < 4; p++) {
            float* o0 = out + (size_t)d[2 * p]     * D_OUT;
            float* o1 = out + (size_t)d[2 * p + 1] * D_OUT;
#pragma unroll
            for (int c = 0; c < 3; c++) {
                float lo, hi;
                UNPACKF2(lo, hi, acc[p][c]);
                if (2 * p     < B) atomicAdd(o0 + lane + 32 * c, lo);
                if (2 * p + 1 < B) atomicAdd(o1 + lane + 32 * c, hi);
            }
        }

        int rem = q - B;
        int tmp = 0;
        __syncwarp();
        if (lane < rem) tmp = eidx[wid][B + lane];
        __syncwarp();
        if (lane < rem) eidx[wid][lane] = tmp;
        __syncwarp();
        q = rem;
    }
}

// ---------------------------------------------------------------------------
extern "C" void kernel_launch(void* const* d_in, const int* in_sizes, int n_in,
                              void* d_out, int out_size)
{
    const float* x   = (const float*)d_in[0];          // [N, 96]
    const float* ef  = (const float*)d_in[1];          // [N, 32]
    const int*   ei  = (const int*)  d_in[2];          // [2, E]
    const int*   et  = (const int*)  d_in[3];          // [E]
    const float* W   = (const float*)d_in[4];          // [4, 128, 96]
    const float* b   = (const float*)d_in[5];          // [4, 96]
    float*       out = (float*)d_out;                  // [N, 96]

    const int* srcp = ei;
    const int* dstp = ei + N_EDGES;

    cudaMemsetAsync(out, 0, (size_t)out_size * sizeof(float), 0);

    {
        dim3 grid((N_NODES + 63) / 64, N_TYPES);
        precompute_y_kernel<<<grid, 256>>>(x, W, b);
    }
    {
        dim3 grid(296, N_TYPES);
        edge_kernel<<<grid, 256>>>(ef, srcp, dstp, et, W, out);
    }
}

// round 5
// speedup vs baseline: 1.3040x; 1.0564x over previous
#include <cuda_runtime.h>
#include <cuda_bf16.h>

#define N_NODES 50000
#define N_EDGES 800000
#define D_IN    96
#define D_EDGE  32
#define D_OUT   96
#define N_TYPES 4

typedef unsigned long long ull;

#define PACKF2(dst, lo, hi) \
    asm("mov.b64 %0, {%1, %2};" : "=l"(dst) : "f"(lo), "f"(hi))
#define UNPACKF2(lo, hi, src) \
    asm("mov.b64 {%0, %1}, %2;" : "=f"(lo), "=f"(hi) : "l"(src))
// packed dual-FMA: acc.lo += a.lo*b.lo ; acc.hi += a.hi*b.hi
#define FFMA2(acc, a, b) \
    asm("fma.rn.f32x2 %0, %1, %2, %0;" : "+l"(acc) : "l"(a), "l"(b))

// Scratch: y[t][n][j] = 0.25 * (x[n] @ W_x[t] + b[t])   (76.8 MB, L2-resident)
__device__ float g_y[(size_t)N_TYPES * N_NODES * D_OUT];
// Per-type edge lists: {src, dst} packed
__device__ int2 g_elist[N_TYPES][N_EDGES];
__device__ int  g_ecount[N_TYPES];

// ---------------------------------------------------------------------------
__global__ void zero_counts_kernel() {
    if (threadIdx.x < N_TYPES) g_ecount[threadIdx.x] = 0;
}

// ---------------------------------------------------------------------------
// Partition edges by type into g_elist. Block-aggregated base reservation:
// phase1 count (warp ballots -> smem), phase2 one global atomicAdd per type
// per block, phase3 rescan + write at reserved offsets.
// ---------------------------------------------------------------------------
__global__ __launch_bounds__(256) void partition_kernel(
    const int* __restrict__ src,
    const int* __restrict__ dst,
    const int* __restrict__ et)
{
    __shared__ int cnt[N_TYPES];
    __shared__ int off[N_TYPES];

    if (threadIdx.x < N_TYPES) cnt[threadIdx.x] = 0;
    __syncthreads();

    const int per_block = (N_EDGES + gridDim.x - 1) / gridDim.x;
    const int lo = blockIdx.x * per_block;
    const int hi = min(lo + per_block, N_EDGES);
    const int lane = threadIdx.x & 31;
    const int wid  = threadIdx.x >> 5;
    const unsigned lt = (1u << lane) - 1u;

    // phase 1: count per type
    for (int ib = lo + wid * 32; ib < hi; ib += 256) {
        int i = ib + lane;
        bool v = (i < hi);
        int tt = v ? et[i] : -1;
#pragma unroll
        for (int t = 0; t < N_TYPES; t++) {
            unsigned m = __ballot_sync(0xffffffffu, tt == t);
            if (m && lane == (__ffs(m) - 1))
                atomicAdd(&cnt[t], __popc(m));
        }
    }
    __syncthreads();

    // phase 2: reserve global ranges
    if (threadIdx.x < N_TYPES)
        off[threadIdx.x] = atomicAdd(&g_ecount[threadIdx.x], cnt[threadIdx.x]);
    __syncthreads();

    // phase 3: write
    for (int ib = lo + wid * 32; ib < hi; ib += 256) {
        int i = ib + lane;
        bool v = (i < hi);
        int tt = v ? et[i] : -1;
        int s = 0, d = 0;
        if (v) { s = src[i]; d = dst[i]; }
#pragma unroll
        for (int t = 0; t < N_TYPES; t++) {
            unsigned m = __ballot_sync(0xffffffffu, tt == t);
            if (!m) continue;
            int leader = __ffs(m) - 1;
            int base = 0;
            if (lane == leader) base = atomicAdd(&off[t], __popc(m));
            base = __shfl_sync(0xffffffffu, base, leader);
            if (tt == t)
                g_elist[t][base + __popc(m & lt)] = make_int2(s, d);
        }
    }
}

// ---------------------------------------------------------------------------
// Kernel A: y[t][n] = 0.25*(x[n] @ W_x[t] + b[t]),  NODE-PAIR packed FFMA2.
// x tile transposed xs_t[k][node], stride 68 (16B-aligned rows so node pairs
// load via one LDS.128 broadcast serving 2 accumulator pairs).
// ---------------------------------------------------------------------------
#define XT_STRIDE 68

__global__ __launch_bounds__(256) void precompute_y_kernel(
    const float* __restrict__ x,      // [N, 96]
    const float* __restrict__ W,      // [4, 128, 96]
    const float* __restrict__ b)      // [4, 96]
{
    const int t     = blockIdx.y;
    const int node0 = blockIdx.x * 64;

    __shared__ float Wsm[D_IN][D_OUT];                      // 36 KB (0.25*W_x)
    __shared__ __align__(16) float xs_t[D_IN][XT_STRIDE];   // 26.1 KB
    __shared__ float bsm[D_OUT];

    const float* Wt = W + (size_t)t * 128 * 96;
    for (int i = threadIdx.x; i < D_IN * D_OUT; i += blockDim.x)
        (&Wsm[0][0])[i] = 0.25f * Wt[i];
    if (threadIdx.x < D_OUT)
        bsm[threadIdx.x] = 0.25f * b[t * D_OUT + threadIdx.x];
    for (int i = threadIdx.x; i < 64 * D_IN; i += blockDim.x) {
        int r = i / D_IN, c = i - r * D_IN;
        int n = node0 + r;
        xs_t[c][r] = (n < N_NODES) ? x[(size_t)n * D_IN + c] : 0.0f;
    }
    __syncthreads();

    const int wid  = threadIdx.x >> 5;
    const int lane = threadIdx.x & 31;
    const int i0   = wid * 8;                 // 8 nodes per warp = 4 pairs

    ull acc[4][3];
    {
        float b0 = bsm[lane], b1 = bsm[lane + 32], b2 = bsm[lane + 64];
        ull B0, B1, B2;
        PACKF2(B0, b0, b0); PACKF2(B1, b1, b1); PACKF2(B2, b2, b2);
#pragma unroll
        for (int p = 0; p < 4; p++) { acc[p][0] = B0; acc[p][1] = B1; acc[p][2] = B2; }
    }

#pragma unroll 8
    for (int k = 0; k < D_IN; k++) {
        float w0 = Wsm[k][lane];
        float w1 = Wsm[k][lane + 32];
        float w2 = Wsm[k][lane + 64];
        ull W0, W1, W2;
        PACKF2(W0, w0, w0); PACKF2(W1, w1, w1); PACKF2(W2, w2, w2);
#pragma unroll
        for (int h = 0; h < 2; h++) {
            ulonglong2 xv = *reinterpret_cast<const ulonglong2*>(&xs_t[k][i0 + 4 * h]);
            FFMA2(acc[2 * h][0],     xv.x, W0);
            FFMA2(acc[2 * h][1],     xv.x, W1);
            FFMA2(acc[2 * h][2],     xv.x, W2);
            FFMA2(acc[2 * h + 1][0], xv.y, W0);
            FFMA2(acc[2 * h + 1][1], xv.y, W1);
            FFMA2(acc[2 * h + 1][2], xv.y, W2);
        }
    }

#pragma unroll
    for (int p = 0; p < 4; p++) {
        int n_lo = node0 + i0 + 2 * p;
        int n_hi = n_lo + 1;
        float* y_lo = g_y + ((size_t)t * N_NODES + n_lo) * D_OUT;
        float* y_hi = g_y + ((size_t)t * N_NODES + n_hi) * D_OUT;
#pragma unroll
        for (int c = 0; c < 3; c++) {
            float lo, hi;
            UNPACKF2(lo, hi, acc[p][c]);
            if (n_lo < N_NODES) y_lo[lane + 32 * c] = lo;
            if (n_hi < N_NODES) y_hi[lane + 32 * c] = hi;
        }
    }
}

// ---------------------------------------------------------------------------
// Kernel B: edge kernel over pre-partitioned per-type lists.
// EDGE-PAIR packed FFMA2; W loaded scalar (LDS.32) + register-duplicated;
// esm broadcast via LDS.128 (one load serves 2 pairs).
// out[dst] += y[t][src] + 0.25 * (|ef[s]-ef[d]| @ W_e[t])
// ---------------------------------------------------------------------------
#define EK_WARPS   8
#define BATCH      8
#define ESM_STRIDE 12   // 48B rows: 16B-aligned, 4-way STS conflict (fill only)

__global__ __launch_bounds__(256) void edge_kernel(
    const float* __restrict__ ef,     // [N, 32]
    const float* __restrict__ W,      // [4, 128, 96]
    float*       __restrict__ out)    // [N, 96]
{
    const int t = blockIdx.y;

    __shared__ float Wsm[D_EDGE][D_OUT];                                  // 12 KB
    __shared__ __align__(16) float esm[EK_WARPS][D_EDGE][ESM_STRIDE];     // 12.3 KB

    // rows 96..127 of W[t] = W_e, pre-scaled by 1/4 (scalar, no duplication)
    const float* Wt = W + (size_t)t * 128 * 96 + 96 * 96;
    for (int i = threadIdx.x; i < D_EDGE * D_OUT; i += blockDim.x)
        (&Wsm[0][0])[i] = 0.25f * Wt[i];
    __syncthreads();

    const int wid  = threadIdx.x >> 5;
    const int lane = threadIdx.x & 31;

    const int  cnt    = g_ecount[t];
    const int2* list  = g_elist[t];
    const long stride = (long)gridDim.x * EK_WARPS * BATCH;

    for (long base = ((long)blockIdx.x * EK_WARPS + wid) * BATCH;
         base < cnt; base += stride) {

        const int B = min(BATCH, (int)(cnt - base));

        int s[BATCH], d[BATCH];
#pragma unroll
        for (int i = 0; i < BATCH; i++) {
            int j = (i < B) ? i : 0;
            int2 sd = __ldg(&list[base + j]);    // warp-uniform address
            s[i] = sd.x;
            d[i] = sd.y;
            float a  = ef[(size_t)s[i] * D_EDGE + lane];
            float bb = ef[(size_t)d[i] * D_EDGE + lane];
            esm[wid][lane][i] = fabsf(a - bb);
        }
        __syncwarp();

        // acc = (y[src 2p], y[src 2p+1]) packed
        ull acc[4][3];
#pragma unroll
        for (int p = 0; p < 4; p++) {
            const float* y0 = g_y + ((size_t)t * N_NODES + s[2 * p])     * D_OUT;
            const float* y1 = g_y + ((size_t)t * N_NODES + s[2 * p + 1]) * D_OUT;
#pragma unroll
            for (int c = 0; c < 3; c++)
                PACKF2(acc[p][c], y0[lane + 32 * c], y1[lane + 32 * c]);
        }

#pragma unroll 8
        for (int k = 0; k < D_EDGE; k++) {
            float w0 = Wsm[k][lane];
            float w1 = Wsm[k][lane + 32];
            float w2 = Wsm[k][lane + 64];
            ull W0, W1, W2;
            PACKF2(W0, w0, w0); PACKF2(W1, w1, w1); PACKF2(W2, w2, w2);
            // one 16B broadcast serves two edge-pairs
            ulonglong2 eA = *reinterpret_cast<const ulonglong2*>(&esm[wid][k][0]);
            ulonglong2 eB = *reinterpret_cast<const ulonglong2*>(&esm[wid][k][4]);
            FFMA2(acc[0][0], eA.x, W0); FFMA2(acc[0][1], eA.x, W1); FFMA2(acc[0][2], eA.x, W2);
            FFMA2(acc[1][0], eA.y, W0); FFMA2(acc[1][1], eA.y, W1); FFMA2(acc[1][2], eA.y, W2);
            FFMA2(acc[2][0], eB.x, W0); FFMA2(acc[2][1], eB.x, W1); FFMA2(acc[2][2], eB.x, W2);
            FFMA2(acc[3][0], eB.y, W0); FFMA2(acc[3][1], eB.y, W1); FFMA2(acc[3][2], eB.y, W2);
        }

#pragma unroll
        for (int p = 0; p < 4; p++) {
            float* o0 = out + (size_t)d[2 * p]     * D_OUT;
            float* o1 = out + (size_t)d[2 * p + 1] * D_OUT;
#pragma unroll
            for (int c = 0; c < 3; c++) {
                float lo, hi;
                UNPACKF2(lo, hi, acc[p][c]);
                if (2 * p     < B) atomicAdd(o0 + lane + 32 * c, lo);
                if (2 * p + 1 < B) atomicAdd(o1 + lane + 32 * c, hi);
            }
        }
        __syncwarp();   // protect esm before next iteration's fill
    }
}

// ---------------------------------------------------------------------------
extern "C" void kernel_launch(void* const* d_in, const int* in_sizes, int n_in,
                              void* d_out, int out_size)
{
    const float* x   = (const float*)d_in[0];          // [N, 96]
    const float* ef  = (const float*)d_in[1];          // [N, 32]
    const int*   ei  = (const int*)  d_in[2];          // [2, E]
    const int*   et  = (const int*)  d_in[3];          // [E]
    const float* W   = (const float*)d_in[4];          // [4, 128, 96]
    const float* b   = (const float*)d_in[5];          // [4, 96]
    float*       out = (float*)d_out;                  // [N, 96]

    const int* srcp = ei;
    const int* dstp = ei + N_EDGES;

    cudaMemsetAsync(out, 0, (size_t)out_size * sizeof(float), 0);

    zero_counts_kernel<<<1, 32>>>();
    partition_kernel<<<296, 256>>>(srcp, dstp, et);
    {
        dim3 grid((N_NODES + 63) / 64, N_TYPES);
        precompute_y_kernel<<<grid, 256>>>(x, W, b);
    }
    {
        dim3 grid(74, N_TYPES);
        edge_kernel<<<grid, 256>>>(ef, W, out);
    }
}

// round 6
// speedup vs baseline: 1.3421x; 1.0292x over previous
#include <cuda_runtime.h>
#include <cuda_bf16.h>

#define N_NODES 50000
#define N_EDGES 800000
#define D_IN    96
#define D_EDGE  32
#define D_OUT   96
#define D_FEAT  128          // D_IN + D_EDGE, matches W's K dimension
#define N_TYPES 4

typedef unsigned long long ull;

#define PACKF2(dst, lo, hi) \
    asm("mov.b64 %0, {%1, %2};" : "=l"(dst) : "f"(lo), "f"(hi))
#define UNPACKF2(lo, hi, src) \
    asm("mov.b64 {%0, %1}, %2;" : "=f"(lo), "=f"(hi) : "l"(src))
// packed dual-FMA: acc.lo += a.lo*b.lo ; acc.hi += a.hi*b.hi
#define FFMA2(acc, a, b) \
    asm("fma.rn.f32x2 %0, %1, %2, %0;" : "+l"(acc) : "l"(a), "l"(b))

// feat[t][n][0:96] = sum of x[src] over type-t edges into n
// feat[t][n][96:128] = sum of |ef[src]-ef[dst]| over those edges
// followed by cnt[t][n] (edge counts as float)
#define FEAT_ELEMS ((size_t)N_TYPES * N_NODES * D_FEAT)
#define CNT_OFFSET FEAT_ELEMS
__device__ float g_scratch[FEAT_ELEMS + (size_t)N_TYPES * N_NODES];

// ---------------------------------------------------------------------------
// Kernel 1: edge scatter. One warp processes 4 edges per iteration.
// Per edge: feat[t][dst][lane]      += x[src][lane] (3 x 32 lanes)
//           feat[t][dst][96+lane]   += |ef[src][lane]-ef[dst][lane]|
//           cnt[t][dst]             += 1
// All atomics are warp-coalesced 128B rows.
// ---------------------------------------------------------------------------
#define SC_BATCH 4

__global__ __launch_bounds__(256) void scatter_kernel(
    const float* __restrict__ x,      // [N, 96]
    const float* __restrict__ ef,     // [N, 32]
    const int*   __restrict__ src,    // [E]
    const int*   __restrict__ dst,    // [E]
    const int*   __restrict__ et)     // [E]
{
    const int lane = threadIdx.x & 31;
    const int gw   = (blockIdx.x * blockDim.x + threadIdx.x) >> 5;
    const int nw   = (gridDim.x * blockDim.x) >> 5;

    float* cnt = g_scratch + CNT_OFFSET;

    for (long e0 = (long)gw * SC_BATCH; e0 < N_EDGES; e0 += (long)nw * SC_BATCH) {
        int  s[SC_BATCH], d[SC_BATCH], t[SC_BATCH];
        bool v[SC_BATCH];
#pragma unroll
        for (int i = 0; i < SC_BATCH; i++) {
            long e = e0 + i;
            v[i] = (e < N_EDGES);
            long ec = v[i] ? e : 0;
            s[i] = __ldg(&src[ec]);
            d[i] = __ldg(&dst[ec]);
            t[i] = __ldg(&et[ec]);
        }
#pragma unroll
        for (int i = 0; i < SC_BATCH; i++) {
            if (!v[i]) continue;
            const float* xr = x  + (size_t)s[i] * D_IN;
            float x0 = xr[lane], x1 = xr[lane + 32], x2 = xr[lane + 64];
            float ea = ef[(size_t)s[i] * D_EDGE + lane];
            float eb = ef[(size_t)d[i] * D_EDGE + lane];
            float ev = fabsf(ea - eb);

            float* row = g_scratch + ((size_t)t[i] * N_NODES + d[i]) * D_FEAT;
            atomicAdd(row + lane,      x0);
            atomicAdd(row + lane + 32, x1);
            atomicAdd(row + lane + 64, x2);
            atomicAdd(row + lane + 96, ev);
            if (lane == 0)
                atomicAdd(&cnt[(size_t)t[i] * N_NODES + d[i]], 1.0f);
        }
    }
}

// ---------------------------------------------------------------------------
// Kernel 2: out[n] = sum_t ( feat[t][n] @ 0.25*W[t] + cnt[t][n]*0.25*b[t] ).
// One block per 64-node tile; loops over the 4 types, accumulating in
// node-pair packed FFMA2 registers; single clean store (no atomics, no memset).
// Dynamic smem: xs_t[128][68] transposed feat tile + Wsm[128][96] + bsm + csm.
// ---------------------------------------------------------------------------
#define XT_STRIDE 68
#define SM_XS   (D_FEAT * XT_STRIDE)          // 8704 floats
#define SM_W    (D_FEAT * D_OUT)              // 12288 floats
#define GEMM_SMEM_BYTES ((SM_XS + SM_W + D_OUT + 64) * 4)

__global__ __launch_bounds__(256) void gemm_kernel(
    const float* __restrict__ W,      // [4, 128, 96]
    const float* __restrict__ b,      // [4, 96]
    float*       __restrict__ out)    // [N, 96]
{
    extern __shared__ __align__(16) float smem[];
    float (*xs)[XT_STRIDE] = (float(*)[XT_STRIDE])smem;       // [128][68]
    float* Wsm = smem + SM_XS;                                 // [128*96]
    float* bsm = smem + SM_XS + SM_W;                          // [96]
    float* csm = bsm + D_OUT;                                  // [64]

    const int node0 = blockIdx.x * 64;
    const int wid   = threadIdx.x >> 5;
    const int lane  = threadIdx.x & 31;
    const int i0    = wid * 8;                // 8 nodes per warp = 4 pairs

    const float* cnt = g_scratch + CNT_OFFSET;

    ull acc[4][3];
#pragma unroll
    for (int p = 0; p < 4; p++)
        acc[p][0] = acc[p][1] = acc[p][2] = 0ull;

    for (int t = 0; t < N_TYPES; t++) {
        __syncthreads();   // previous type's reads done before refill

        const float* Wt = W + (size_t)t * D_FEAT * D_OUT;
        for (int i = threadIdx.x; i < D_FEAT * D_OUT; i += blockDim.x)
            Wsm[i] = 0.25f * Wt[i];
        if (threadIdx.x < D_OUT)
            bsm[threadIdx.x] = 0.25f * b[t * D_OUT + threadIdx.x];
        if (threadIdx.x < 64) {
            int n = node0 + threadIdx.x;
            csm[threadIdx.x] = (n < N_NODES)
                ? cnt[(size_t)t * N_NODES + n] : 0.0f;
        }
        // transposed feat tile: coalesced gmem read, strided STS (one-time)
        const float* ft = g_scratch + (size_t)t * N_NODES * D_FEAT;
        for (int i = threadIdx.x; i < 64 * D_FEAT; i += blockDim.x) {
            int r = i >> 7, k = i & 127;
            int n = node0 + r;
            xs[k][r] = (n < N_NODES) ? ft[(size_t)n * D_FEAT + k] : 0.0f;
        }
        __syncthreads();

#pragma unroll 8
        for (int k = 0; k < D_FEAT; k++) {
            float w0 = Wsm[k * D_OUT + lane];
            float w1 = Wsm[k * D_OUT + lane + 32];
            float w2 = Wsm[k * D_OUT + lane + 64];
            ull W0, W1, W2;
            PACKF2(W0, w0, w0); PACKF2(W1, w1, w1); PACKF2(W2, w2, w2);
#pragma unroll
            for (int h = 0; h < 2; h++) {
                ulonglong2 xv = *reinterpret_cast<const ulonglong2*>(&xs[k][i0 + 4 * h]);
                FFMA2(acc[2 * h][0],     xv.x, W0);
                FFMA2(acc[2 * h][1],     xv.x, W1);
                FFMA2(acc[2 * h][2],     xv.x, W2);
                FFMA2(acc[2 * h + 1][0], xv.y, W0);
                FFMA2(acc[2 * h + 1][1], xv.y, W1);
                FFMA2(acc[2 * h + 1][2], xv.y, W2);
            }
        }

        // bias: acc[p][c] += pack(cnt_lo, cnt_hi) * pack(b_c, b_c)
        float bb0 = bsm[lane], bb1 = bsm[lane + 32], bb2 = bsm[lane + 64];
        ull B0, B1, B2;
        PACKF2(B0, bb0, bb0); PACKF2(B1, bb1, bb1); PACKF2(B2, bb2, bb2);
#pragma unroll
        for (int p = 0; p < 4; p++) {
            ull CN;
            PACKF2(CN, csm[i0 + 2 * p], csm[i0 + 2 * p + 1]);
            FFMA2(acc[p][0], CN, B0);
            FFMA2(acc[p][1], CN, B1);
            FFMA2(acc[p][2], CN, B2);
        }
    }

#pragma unroll
    for (int p = 0; p < 4; p++) {
        int n_lo = node0 + i0 + 2 * p;
        int n_hi = n_lo + 1;
        float* o_lo = out + (size_t)n_lo * D_OUT;
        float* o_hi = out + (size_t)n_hi * D_OUT;
#pragma unroll
        for (int c = 0; c < 3; c++) {
            float lo, hi;
            UNPACKF2(lo, hi, acc[p][c]);
            if (n_lo < N_NODES) o_lo[lane + 32 * c] = lo;
            if (n_hi < N_NODES) o_hi[lane + 32 * c] = hi;
        }
    }
}

// ---------------------------------------------------------------------------
extern "C" void kernel_launch(void* const* d_in, const int* in_sizes, int n_in,
                              void* d_out, int out_size)
{
    const float* x   = (const float*)d_in[0];          // [N, 96]
    const float* ef  = (const float*)d_in[1];          // [N, 32]
    const int*   ei  = (const int*)  d_in[2];          // [2, E]
    const int*   et  = (const int*)  d_in[3];          // [E]
    const float* W   = (const float*)d_in[4];          // [4, 128, 96]
    const float* b   = (const float*)d_in[5];          // [4, 96]
    float*       out = (float*)d_out;                  // [N, 96]

    const int* srcp = ei;
    const int* dstp = ei + N_EDGES;

    // zero the aggregation scratch (feat + cnt)
    void* scratch_ptr = nullptr;
    cudaGetSymbolAddress(&scratch_ptr, g_scratch);
    cudaMemsetAsync(scratch_ptr, 0, sizeof(g_scratch), 0);

    scatter_kernel<<<592, 256>>>(x, ef, srcp, dstp, et);

    static int smem_set = 0;
    if (!smem_set) {
        cudaFuncSetAttribute(gemm_kernel,
                             cudaFuncAttributeMaxDynamicSharedMemorySize,
                             GEMM_SMEM_BYTES);
        smem_set = 1;
    }
    gemm_kernel<<<(N_NODES + 63) / 64, 256, GEMM_SMEM_BYTES>>>(W, b, out);
}